// round 16
// baseline (speedup 1.0000x reference)
#include <cuda_runtime.h>
#include <cuda_bf16.h>
#include <cstdint>

// ---------------------------------------------------------------------------
// OrdinalPeakedCELoss — R11 skeleton + full/empty barrier decoupling (v7).
//  Record: R11 (TILE=512, 2-stage, 740 blk) = 37.4us best; R12/13/14 all
//  regressed by changing tile/copy shape. R12 isolated the residual loss:
//  block-wide __syncthreads couples all warps to the slowest at every tile.
//  v7 changes EXACTLY one thing vs R11: the coupling.
//   * empty[s] mbarrier (count=8): each warp's lane0 arrives after reading
//   * producer (tid0) waits empty[s] before refilling stage s (tile j+2)
//   * consumer warps never wait on siblings -> no __syncthreads in the loop
//  Compute body, tiling, copy granularity, reduction: identical to R11.
// ---------------------------------------------------------------------------

#define KCLS 9
#define NTHREADS 256
#define NWARPS (NTHREADS / 32)
#define TILE 512
#define ROWS_PT 2
#define NSTAGES 2
#define PAD 4                                    /* guard floats each side  */
#define LOG_FLOATS (TILE * KCLS)                 /* 4608 */
#define LOG_BYTES (LOG_FLOATS * 4)               /* 18432 */
#define Y_BYTES   (TILE * 4)                     /* 2048  */
#define TX_BYTES  (LOG_BYTES + Y_BYTES)
#define NBLK 740

#define ALPHA_C       0.4f
#define W_FAR_C       7.0f
#define DELTA_FAR_C   0.15f
#define W_TAIL_C      9.0f
#define W_LPEAK_C     12.0f
#define PROB_MARGIN_C 0.35f
#define W_EMD_C       1.2f
#define LOG2E_C       1.4426950408889634f
#define LN2_LN9_C     0.31546487678572877f

#define AWF (ALPHA_C * W_FAR_C)
#define AWT (ALPHA_C * W_TAIL_C)
#define AWL (ALPHA_C * W_LPEAK_C)
#define AWE (ALPHA_C * W_EMD_C)

__device__ float        g_partials[NBLK];
__device__ unsigned int g_count = 0;

__device__ __forceinline__ float f_ex2(float x){ float r; asm("ex2.approx.ftz.f32 %0, %1;" : "=f"(r) : "f"(x)); return r; }
__device__ __forceinline__ float f_lg2(float x){ float r; asm("lg2.approx.ftz.f32 %0, %1;" : "=f"(r) : "f"(x)); return r; }
__device__ __forceinline__ float f_rcp(float x){ float r; asm("rcp.approx.ftz.f32 %0, %1;" : "=f"(r) : "f"(x)); return r; }

__device__ __forceinline__ uint32_t smem_u32(const void* p) {
    uint32_t a;
    asm("{ .reg .u64 t; cvta.to.shared.u64 t, %1; cvt.u32.u64 %0, t; }" : "=r"(a) : "l"(p));
    return a;
}

#define MBAR_INIT(bar, cnt) \
    asm volatile("mbarrier.init.shared.b64 [%0], %1;" :: "r"(bar), "r"(cnt) : "memory")
#define MBAR_EXPECT_TX(bar, bytes) \
    asm volatile("mbarrier.arrive.expect_tx.shared.b64 _, [%0], %1;" :: "r"(bar), "r"(bytes) : "memory")
#define MBAR_ARRIVE(bar) \
    asm volatile("mbarrier.arrive.release.cta.shared::cta.b64 _, [%0];" :: "r"(bar) : "memory")
#define MBAR_WAIT(bar, ph) do {                                                   \
    asm volatile("{\n\t.reg .pred P;\n"                                           \
        "W_%=:\n\t"                                                               \
        "mbarrier.try_wait.parity.acquire.cta.shared::cta.b64 P, [%0], %1, 0x989680;\n\t" \
        "@P bra D_%=;\n\t"                                                        \
        "bra W_%=;\n"                                                             \
        "D_%=:\n\t}"                                                              \
        :: "r"(bar), "r"(ph) : "memory");                                         \
} while (0)
#define BULK_CP(dst, src, bytes, bar) \
    asm volatile("cp.async.bulk.shared::cta.global.mbarrier::complete_tx::bytes [%0], [%1], %2, [%3];" \
        :: "r"(dst), "l"(src), "r"(bytes), "r"(bar) : "memory")

__device__ __forceinline__ float cw_of(int k) {
    const float cw[KCLS] = {
        3.0f/95.0f, 7.0f/95.0f, 10.0f/95.0f, 10.0f/95.0f, 10.0f/95.0f,
        10.0f/95.0f, 10.0f/95.0f, 10.0f/95.0f, 25.0f/95.0f };
    return cw[k];
}

// Hot path: lrow readable at [-1] and [9] (padded tile; OOR finite, masked).
__device__ __forceinline__ float row_loss(const float* __restrict__ lrow, int y,
                                          const float* __restrict__ s_ccw) {
    const float fy  = (float)y;
    const float fy1 = fy + 1.0f;

    float E = 0.0f, Q = 0.0f, A = 0.0f, tail = 0.0f, ef = 0.0f;

#pragma unroll
    for (int k = 0; k < KCLS; ++k) {
        float e = f_ex2(lrow[k] * LOG2E_C);            // exp(l_k)
        E += e;                                         // prefix; E_8 == S
        float u = cw_of(k) * E;                         // FMUL imm
        Q = fmaf(u, E, Q);                              // sum cw_k E_k^2
        float le = __saturatef(fy1 - (float)k);         // 1 iff k<=y
        A = fmaf(le, u, A);
        float s = fabsf((float)k - fy) - 1.0f;          // |d|-1
        float c = fmaxf(s, 0.0f);
        float h = e * c;
        ef = fmaxf(ef, fminf(h, e));                    // e*min(c,1)
        tail = fmaf(h, c * c, tail);                    // e*(|d|-1)^3
    }

    float invS = f_rcp(E);
    float ty = lrow[y] * LOG2E_C;
    float ey = f_ex2(ty);
    float el = f_ex2(lrow[y - 1] * LOG2E_C) * __saturatef(fy);         // 0 at y=0
    float er = f_ex2(lrow[y + 1] * LOG2E_C) * __saturatef(8.0f - fy);  // 0 at y=8
    float en = fmaxf(el, er);

    float farm  = fmaxf(fmaf(ef - ey, invS, DELTA_FAR_C),   0.0f);
    float lpeak = fmaxf(fmaf(en - ey, invS, PROB_MARGIN_C), 0.0f);
    float emd   = fmaf(Q, invS * invS, fmaf(-2.0f * A, invS, s_ccw[y]));

    float r = (f_lg2(E) - ty) * LN2_LN9_C;              // nll / ln 9
    r = fmaf(AWF, farm, r);
    r = fmaf(AWT, tail * invS, r);
    r = fmaf(AWL, lpeak, r);
    r = fmaf(AWE, emd, r);
    return r;
}

// Residue path (rare): clamped indices, direct global reads.
__device__ __noinline__ float row_loss_global(const float* __restrict__ g, int y,
                                              const float* __restrict__ s_ccw) {
    const float fy = (float)y;
    float E = 0.0f, Q = 0.0f, A = 0.0f, tail = 0.0f, ef = 0.0f;
    float lv[KCLS];
#pragma unroll
    for (int k = 0; k < KCLS; ++k) lv[k] = __ldg(&g[k]);
#pragma unroll
    for (int k = 0; k < KCLS; ++k) {
        float e = f_ex2(lv[k] * LOG2E_C);
        E += e;
        float u = cw_of(k) * E;
        Q = fmaf(u, E, Q);
        float le = __saturatef(fy + 1.0f - (float)k);
        A = fmaf(le, u, A);
        float s = fabsf((float)k - fy) - 1.0f;
        float c = fmaxf(s, 0.0f);
        float h = e * c;
        ef = fmaxf(ef, fminf(h, e));
        tail = fmaf(h, c * c, tail);
    }
    float invS = f_rcp(E);
    int yl = (y > 0) ? y - 1 : 0;
    int yr = (y < KCLS - 1) ? y + 1 : KCLS - 1;
    float ty = lv[y] * LOG2E_C;
    float ey = f_ex2(ty);
    float el = f_ex2(lv[yl] * LOG2E_C) * __saturatef(fy);
    float er = f_ex2(lv[yr] * LOG2E_C) * __saturatef(8.0f - fy);
    float en = fmaxf(el, er);
    float farm  = fmaxf(fmaf(ef - ey, invS, DELTA_FAR_C),   0.0f);
    float lpeak = fmaxf(fmaf(en - ey, invS, PROB_MARGIN_C), 0.0f);
    float emd   = fmaf(Q, invS * invS, fmaf(-2.0f * A, invS, s_ccw[y]));
    float r = (f_lg2(E) - ty) * LN2_LN9_C;
    r = fmaf(AWF, farm, r);
    r = fmaf(AWT, tail * invS, r);
    r = fmaf(AWL, lpeak, r);
    r = fmaf(AWE, emd, r);
    return r;
}

__global__ __launch_bounds__(NTHREADS, 5)
void opcel_pipe(const float* __restrict__ logits,
                const int*   __restrict__ y,
                float*       __restrict__ out,
                int B, int nblocks) {
    __shared__ __align__(16) float s_log[NSTAGES][LOG_FLOATS + 2 * PAD];
    __shared__ __align__(16) int   s_y[NSTAGES][TILE];
    __shared__ __align__(8)  unsigned long long s_full[NSTAGES];
    __shared__ __align__(8)  unsigned long long s_empty[NSTAGES];
    __shared__ float s_ccw[KCLS];
    __shared__ float s_red[NWARPS];
    __shared__ int   s_last;

    const int tid  = threadIdx.x;
    const int bid  = blockIdx.x;
    const int lane = tid & 31;
    const int wid  = tid >> 5;

    if (tid < KCLS) {
        const float ccw[KCLS] = {
            3.0f/95.0f, 10.0f/95.0f, 20.0f/95.0f, 30.0f/95.0f, 40.0f/95.0f,
            50.0f/95.0f, 60.0f/95.0f, 70.0f/95.0f, 1.0f };
        s_ccw[tid] = ccw[tid];
    }
    if (tid < PAD) {
#pragma unroll
        for (int s = 0; s < NSTAGES; ++s) {
            s_log[s][tid] = 0.0f;
            s_log[s][PAD + LOG_FLOATS + tid] = 0.0f;
        }
    }
    if (tid < NSTAGES) {
        MBAR_INIT(smem_u32(&s_full[tid]), 1);
        MBAR_INIT(smem_u32(&s_empty[tid]), NWARPS);
    }
    __syncthreads();

    const uint32_t fb0 = smem_u32(&s_full[0]),  fb1 = smem_u32(&s_full[1]);
    const uint32_t eb0 = smem_u32(&s_empty[0]), eb1 = smem_u32(&s_empty[1]);
    const uint32_t d_log0 = smem_u32(&s_log[0][PAD]);
    const uint32_t d_log1 = smem_u32(&s_log[1][PAD]);
    const uint32_t d_y0   = smem_u32(&s_y[0][0]);
    const uint32_t d_y1   = smem_u32(&s_y[1][0]);

    const int ntiles = B / TILE;
    int my_n = 0;
    for (long long t = bid; t < ntiles; t += nblocks) ++my_n;

    // Prologue: fill both stages (tiles 0 and 1) — no empty-wait on first fill.
    if (tid == 0) {
        if (my_n > 0) {
            long long t0 = bid;
            MBAR_EXPECT_TX(fb0, TX_BYTES);
            BULK_CP(d_log0, (const void*)(logits + t0 * (TILE * KCLS)), LOG_BYTES, fb0);
            BULK_CP(d_y0,   (const void*)(y + t0 * TILE),               Y_BYTES,  fb0);
        }
        if (my_n > 1) {
            long long t1 = (long long)bid + nblocks;
            MBAR_EXPECT_TX(fb1, TX_BYTES);
            BULK_CP(d_log1, (const void*)(logits + t1 * (TILE * KCLS)), LOG_BYTES, fb1);
            BULK_CP(d_y1,   (const void*)(y + t1 * TILE),               Y_BYTES,  fb1);
        }
    }

    float acc = 0.0f;
    int phf0 = 0, phf1 = 0;        /* per-warp full phases  */
    int phe0 = 0, phe1 = 0;        /* producer empty phases */

    for (int j = 0; j < my_n; ++j) {
        const int s = j & 1;

        // Consume: wait this stage full (per-warp phase).
        if (s == 0) { MBAR_WAIT(fb0, phf0); phf0 ^= 1; }
        else        { MBAR_WAIT(fb1, phf1); phf1 ^= 1; }

        const float* lg = &s_log[s][PAD];
        const int*   yt = s_y[s];
#pragma unroll
        for (int jj = 0; jj < ROWS_PT; ++jj) {
            int lr = tid + jj * NTHREADS;   /* stride-9-word rows: conflict-free */
            acc += row_loss(lg + lr * KCLS, yt[lr], s_ccw);
        }
        if (lane == 0) MBAR_ARRIVE(s == 0 ? eb0 : eb1);   /* this warp done w/ stage s */

        // Produce tile j+2 into stage s: only tid0's warp absorbs the drain wait;
        // other warps proceed to stage s^1 (already full) without blocking.
        if (tid == 0 && (j + 2) < my_n) {
            long long tn = (long long)bid + (long long)(j + 2) * nblocks;
            if (s == 0) {
                MBAR_WAIT(eb0, phe0); phe0 ^= 1;
                MBAR_EXPECT_TX(fb0, TX_BYTES);
                BULK_CP(d_log0, (const void*)(logits + tn * (TILE * KCLS)), LOG_BYTES, fb0);
                BULK_CP(d_y0,   (const void*)(y + tn * TILE),               Y_BYTES,  fb0);
            } else {
                MBAR_WAIT(eb1, phe1); phe1 ^= 1;
                MBAR_EXPECT_TX(fb1, TX_BYTES);
                BULK_CP(d_log1, (const void*)(logits + tn * (TILE * KCLS)), LOG_BYTES, fb1);
                BULK_CP(d_y1,   (const void*)(y + tn * TILE),               Y_BYTES,  fb1);
            }
        }
    }

    // Residue rows (B % TILE) -> block 0, direct global reads.
    if (bid == 0) {
        for (int r = ntiles * TILE + tid; r < B; r += NTHREADS)
            acc += row_loss_global(logits + (long long)r * KCLS, __ldg(&y[r]), s_ccw);
    }

    // Block reduction
#pragma unroll
    for (int off = 16; off > 0; off >>= 1)
        acc += __shfl_down_sync(0xFFFFFFFFu, acc, off);
    if (lane == 0) s_red[wid] = acc;
    __syncthreads();
    if (tid == 0) {
        float v = 0.0f;
#pragma unroll
        for (int w = 0; w < NWARPS; ++w) v += s_red[w];
        g_partials[bid] = v;
        __threadfence();
        unsigned int t = atomicAdd(&g_count, 1u);
        s_last = (t == (unsigned int)(nblocks - 1));
    }
    __syncthreads();

    // Last block: deterministic final reduction in double
    if (s_last) {
        double d = 0.0;
        for (int i = tid; i < nblocks; i += NTHREADS)
            d += (double)g_partials[i];
#pragma unroll
        for (int off = 16; off > 0; off >>= 1)
            d += __shfl_down_sync(0xFFFFFFFFu, d, off);

        __shared__ double s_d[NWARPS];
        if (lane == 0) s_d[wid] = d;
        __syncthreads();
        if (tid == 0) {
            double tot = 0.0;
#pragma unroll
            for (int w = 0; w < NWARPS; ++w) tot += s_d[w];
            out[0] = (float)(tot / (double)B);
            g_count = 0;   /* self-reset for graph replay */
        }
    }
}

extern "C" void kernel_launch(void* const* d_in, const int* in_sizes, int n_in,
                              void* d_out, int out_size) {
    const float* logits = (const float*)d_in[0];
    const int*   y      = (const int*)d_in[1];
    float* out = (float*)d_out;
    int B = in_sizes[1];

    int ntiles = B / TILE;
    int nblocks = NBLK;
    if (nblocks > ntiles && ntiles > 0) nblocks = ntiles;
    if (nblocks < 1) nblocks = 1;

    opcel_pipe<<<nblocks, NTHREADS>>>(logits, y, out, B, nblocks);
}